// round 8
// baseline (speedup 1.0000x reference)
#include <cuda_runtime.h>
#include <cuda_bf16.h>
#include <cstdint>

#define BB 4
#define SS 4096
#define DD 512
#define HH 64

typedef unsigned long long u64;
typedef __nv_bfloat16 bf16;

// Split Q/K/V (Q pre-scaled by log2(e)/8), V transposed [b][h][s].
__device__ __align__(16) bf16 g_qh[BB*SS*HH];
__device__ __align__(16) bf16 g_ql[BB*SS*HH];
__device__ __align__(16) bf16 g_kh[BB*SS*HH];
__device__ __align__(16) bf16 g_kl[BB*SS*HH];
__device__ __align__(16) bf16 g_vth[BB*SS*HH];
__device__ __align__(16) bf16 g_vtl[BB*SS*HH];
// Pre-split transposed weights: [mat][h][d].
__device__ __align__(16) bf16 g_wth[3*HH*DD];
__device__ __align__(16) bf16 g_wtl[3*HH*DD];

// ======================= packed f32x2 / exp2 helpers ========================
__device__ __forceinline__ u64 dup2(float x) {
    u64 r; asm("mov.b64 %0, {%1, %1};" : "=l"(r) : "f"(x)); return r;
}
__device__ __forceinline__ u64 pack2(float x, float y) {
    u64 r; asm("mov.b64 %0, {%1, %2};" : "=l"(r) : "f"(x), "f"(y)); return r;
}
__device__ __forceinline__ float2 unpk2(u64 p) {
    float2 v; asm("mov.b64 {%0, %1}, %2;" : "=f"(v.x), "=f"(v.y) : "l"(p)); return v;
}
__device__ __forceinline__ u64 fma2o(u64 a, u64 b, u64 c) {
    u64 d; asm("fma.rn.f32x2 %0, %1, %2, %3;" : "=l"(d) : "l"(a), "l"(b), "l"(c));
    return d;
}
__device__ __forceinline__ u64 add2(u64 a, u64 b) {
    u64 d; asm("add.rn.f32x2 %0, %1, %2;" : "=l"(d) : "l"(a), "l"(b)); return d;
}
__device__ __forceinline__ u64 exp2pair(u64 y2) {
    const u64 MAGIC = dup2(12582912.0f);
    const u64 NEG1  = dup2(-1.0f);
    u64 t2 = add2(y2, MAGIC);
    u64 g2 = fma2o(MAGIC, NEG1, t2);
    u64 f2 = fma2o(g2, NEG1, y2);
    u64 p = dup2(1.3333558146428443e-3f);
    p = fma2o(p, f2, dup2(9.618129107628477e-3f));
    p = fma2o(p, f2, dup2(5.550410866482158e-2f));
    p = fma2o(p, f2, dup2(2.4022650695910072e-1f));
    p = fma2o(p, f2, dup2(6.931471805599453e-1f));
    p = fma2o(p, f2, dup2(1.0f));
    uint2 tb = *reinterpret_cast<uint2*>(&t2);
    uint2 pb = *reinterpret_cast<uint2*>(&p);
    pb.x += (tb.x << 23);
    pb.y += (tb.y << 23);
    return *reinterpret_cast<u64*>(&pb);
}
__device__ __forceinline__ uint32_t bfpack(float lo, float hi) {
    uint32_t r;
    asm("cvt.rn.bf16x2.f32 %0, %1, %2;" : "=r"(r) : "f"(hi), "f"(lo));
    return r;
}

// ======================= tensor-core primitives =============================
__device__ __forceinline__ uint32_t smem_u32(const void* p) {
    uint32_t a;
    asm("{ .reg .u64 t; cvta.to.shared.u64 t, %1; cvt.u32.u64 %0, t; }"
        : "=r"(a) : "l"(p));
    return a;
}
__device__ __forceinline__ void mma_bf16(float (&d)[4], const uint32_t (&a)[4],
                                         uint32_t b0, uint32_t b1) {
    asm volatile(
        "mma.sync.aligned.m16n8k16.row.col.f32.bf16.bf16.f32 "
        "{%0,%1,%2,%3}, {%4,%5,%6,%7}, {%8,%9}, {%0,%1,%2,%3};"
        : "+f"(d[0]), "+f"(d[1]), "+f"(d[2]), "+f"(d[3])
        : "r"(a[0]), "r"(a[1]), "r"(a[2]), "r"(a[3]), "r"(b0), "r"(b1));
}
__device__ __forceinline__ void ldsm_x4(uint32_t (&r)[4], uint32_t addr) {
    asm volatile("ldmatrix.sync.aligned.m8n8.x4.shared.b16 {%0,%1,%2,%3}, [%4];"
        : "=r"(r[0]), "=r"(r[1]), "=r"(r[2]), "=r"(r[3]) : "r"(addr));
}
__device__ __forceinline__ void cp16(uint32_t saddr, const void* gaddr) {
    asm volatile("cp.async.cg.shared.global [%0], [%1], 16;"
        :: "r"(saddr), "l"(gaddr));
}
#define CP_COMMIT() asm volatile("cp.async.commit_group;" ::: "memory")
#define CP_WAIT(n)  asm volatile("cp.async.wait_group %0;" :: "n"(n) : "memory")

// ---------------------------------------------------------------------------
// Kernel 0: pre-split W (transposed) into bf16 hi/lo. [mat][h][d]
// ---------------------------------------------------------------------------
__global__ void wsplit_kernel(const float* __restrict__ Wq,
                              const float* __restrict__ Wk,
                              const float* __restrict__ Wv) {
    int i = blockIdx.x * 256 + threadIdx.x;
#pragma unroll
    for (int e = 0; e < 4; ++e, i += 24576) {
        int mat = i >> 15;
        int rem = i & 32767;
        int h = rem >> 9;
        int d = rem & 511;
        const float* W = mat == 0 ? Wq : (mat == 1 ? Wk : Wv);
        float v = W[d * 64 + h];
        bf16 hi = __float2bfloat16(v);
        g_wth[i] = hi;
        g_wtl[i] = __float2bfloat16(v - __bfloat162float(hi));
    }
}

// ---------------------------------------------------------------------------
// Kernel 1: QKV projection via HMMA bf16x3 (round-7, verified ~54us).
// ---------------------------------------------------------------------------
#define QKV_XF(s) ((s) * 32768)
#define QKV_W(s)  (65536 + (s) * 49152)
#define QKV_XH    163840
#define QKV_XL    180224
#define QKV_SMEM  196608

__device__ __forceinline__ void qkv_load_x(uint32_t sb, const float* __restrict__ x,
                                           int row0, int kb, int slot, int tid) {
    const int row = tid >> 1;
    const int c0 = (tid & 1) * 8;
    const float* src = x + (size_t)(row0 + row) * 512 + kb * 64 + c0 * 4;
    const uint32_t dst = sb + QKV_XF(slot) + row * 256 + c0 * 16;
#pragma unroll
    for (int c = 0; c < 8; ++c) cp16(dst + c * 16, src + c * 4);
}

__device__ __forceinline__ void qkv_load_w(uint32_t sb, int kb, int slot, int tid) {
#pragma unroll
    for (int u = tid; u < 384; u += 256) {
        const int mat = u >> 7;
        const int half = (u >> 6) & 1;
        const int h = u & 63;
        const bf16* src = (half ? g_wtl : g_wth) + ((size_t)(mat * 64 + h)) * 512 + kb * 64;
        const uint32_t dst = sb + QKV_W(slot) + mat * 16384 + half * 8192 + h * 128;
        const int sw = h & 7;
#pragma unroll
        for (int c = 0; c < 8; ++c) cp16(dst + ((c ^ sw) << 4), src + c * 8);
    }
}

__global__ void __launch_bounds__(256, 1) qkv_kernel(
    const float* __restrict__ x,
    const float* __restrict__ bq, const float* __restrict__ bk,
    const float* __restrict__ bv)
{
    extern __shared__ __align__(1024) unsigned char sm[];
    const uint32_t sb = smem_u32(sm);

    const int tid  = threadIdx.x;
    const int lane = tid & 31;
    const int wid  = tid >> 5;
    const int row0 = blockIdx.x * 128;

    qkv_load_x(sb, x, row0, 0, 0, tid);
    qkv_load_w(sb, 0, 0, tid);
    CP_COMMIT();
    qkv_load_x(sb, x, row0, 1, 1, tid);
    qkv_load_w(sb, 1, 1, tid);
    CP_COMMIT();

    float acc[3][8][4] = {};

    const int g = lane >> 3, l = lane & 7;
    const int rowA = wid * 16 + l + ((g & 1) << 3);
    const int cA = g >> 1;
    const int swA = rowA & 7;
    const int rowB = l + ((g & 2) << 2);
    const int cB = g & 1;
    const int swB = rowB & 7;

    for (int kb = 0; kb < 8; ++kb) {
        CP_WAIT(1);
        __syncthreads();

        {
            const int row = tid >> 1;
            const int p0 = (tid & 1) * 16;
            const float* srow = (const float*)(sm + QKV_XF(kb & 1)) + row * 64;
#pragma unroll
            for (int pp = 0; pp < 16; ++pp) {
                const int cp = p0 + pp;
                float f0 = srow[cp * 2], f1 = srow[cp * 2 + 1];
                uint32_t h = bfpack(f0, f1);
                uint32_t lo = bfpack(f0 - __uint_as_float(h << 16),
                                     f1 - __uint_as_float(h & 0xFFFF0000u));
                const uint32_t a = (uint32_t)(row * 128 +
                                   (((cp >> 2) ^ (row & 7)) << 4) + (cp & 3) * 4);
                *(uint32_t*)(sm + QKV_XH + a) = h;
                *(uint32_t*)(sm + QKV_XL + a) = lo;
            }
        }
        __syncthreads();

        const uint32_t wbase = sb + QKV_W(kb & 1);
#pragma unroll
        for (int kc = 0; kc < 4; ++kc) {
            uint32_t aXH[4], aXL[4];
            const uint32_t offA = (uint32_t)(rowA * 128 +
                                 ((((kc << 1) | cA) ^ swA) << 4));
            ldsm_x4(aXH, sb + QKV_XH + offA);
            ldsm_x4(aXL, sb + QKV_XL + offA);
#pragma unroll
            for (int mat = 0; mat < 3; ++mat) {
#pragma unroll
                for (int jj = 0; jj < 4; ++jj) {
                    const uint32_t offB = (uint32_t)((jj * 16 + rowB) * 128 +
                                         ((((kc << 1) | cB) ^ swB) << 4));
                    uint32_t bh[4], bl[4];
                    ldsm_x4(bh, wbase + mat * 16384 + offB);
                    ldsm_x4(bl, wbase + mat * 16384 + 8192 + offB);
                    mma_bf16(acc[mat][2*jj],   aXH, bh[0], bh[1]);
                    mma_bf16(acc[mat][2*jj+1], aXH, bh[2], bh[3]);
                    mma_bf16(acc[mat][2*jj],   aXH, bl[0], bl[1]);
                    mma_bf16(acc[mat][2*jj+1], aXH, bl[2], bl[3]);
                    mma_bf16(acc[mat][2*jj],   aXL, bh[0], bh[1]);
                    mma_bf16(acc[mat][2*jj+1], aXL, bh[2], bh[3]);
                }
            }
        }
        __syncthreads();

        if (kb + 2 < 8) {
            qkv_load_x(sb, x, row0, kb + 2, kb & 1, tid);
            qkv_load_w(sb, kb + 2, kb & 1, tid);
        }
        CP_COMMIT();
    }

    const float QSC = 0.18033688011112042f;   // log2(e)/8
    const int r = lane >> 2;
    const int cq = (lane & 3);
    const int tok = row0 + wid * 16 + r;
    const int bb = blockIdx.x >> 5;
    const int s  = (row0 & (SS - 1)) + wid * 16 + r;

    uint32_t* qhA = (uint32_t*)(g_qh + (size_t)tok * 64);
    uint32_t* qlA = (uint32_t*)(g_ql + (size_t)tok * 64);
    uint32_t* qhB = (uint32_t*)(g_qh + (size_t)(tok + 8) * 64);
    uint32_t* qlB = (uint32_t*)(g_ql + (size_t)(tok + 8) * 64);
    uint32_t* khA = (uint32_t*)(g_kh + (size_t)tok * 64);
    uint32_t* klA = (uint32_t*)(g_kl + (size_t)tok * 64);
    uint32_t* khB = (uint32_t*)(g_kh + (size_t)(tok + 8) * 64);
    uint32_t* klB = (uint32_t*)(g_kl + (size_t)(tok + 8) * 64);

#pragma unroll
    for (int j = 0; j < 8; ++j) {
        const int u32idx = j * 4 + cq;
        const float2 b2q = ((const float2*)bq)[u32idx];
        const float2 b2k = ((const float2*)bk)[u32idx];
        const float2 b2v = ((const float2*)bv)[u32idx];

        {
            float v0 = (acc[0][j][0] + b2q.x) * QSC;
            float v1 = (acc[0][j][1] + b2q.y) * QSC;
            float v2 = (acc[0][j][2] + b2q.x) * QSC;
            float v3 = (acc[0][j][3] + b2q.y) * QSC;
            uint32_t h0 = bfpack(v0, v1), h1 = bfpack(v2, v3);
            qhA[u32idx] = h0;
            qhB[u32idx] = h1;
            qlA[u32idx] = bfpack(v0 - __uint_as_float(h0 << 16),
                                 v1 - __uint_as_float(h0 & 0xFFFF0000u));
            qlB[u32idx] = bfpack(v2 - __uint_as_float(h1 << 16),
                                 v3 - __uint_as_float(h1 & 0xFFFF0000u));
        }
        {
            float v0 = acc[1][j][0] + b2k.x;
            float v1 = acc[1][j][1] + b2k.y;
            float v2 = acc[1][j][2] + b2k.x;
            float v3 = acc[1][j][3] + b2k.y;
            uint32_t h0 = bfpack(v0, v1), h1 = bfpack(v2, v3);
            khA[u32idx] = h0;
            khB[u32idx] = h1;
            klA[u32idx] = bfpack(v0 - __uint_as_float(h0 << 16),
                                 v1 - __uint_as_float(h0 & 0xFFFF0000u));
            klB[u32idx] = bfpack(v2 - __uint_as_float(h1 << 16),
                                 v3 - __uint_as_float(h1 & 0xFFFF0000u));
        }
        {
            const int c0 = j * 8 + cq * 2;
            float v0 = acc[2][j][0] + b2v.x;
            float v1 = acc[2][j][1] + b2v.y;
            float v2 = acc[2][j][2] + b2v.x;
            float v3 = acc[2][j][3] + b2v.y;
            size_t r0 = ((size_t)(bb * 64 + c0)) * SS;
            size_t r1 = r0 + SS;
            bf16 h;
            h = __float2bfloat16(v0);
            g_vth[r0 + s] = h; g_vtl[r0 + s] = __float2bfloat16(v0 - __bfloat162float(h));
            h = __float2bfloat16(v1);
            g_vth[r1 + s] = h; g_vtl[r1 + s] = __float2bfloat16(v1 - __bfloat162float(h));
            h = __float2bfloat16(v2);
            g_vth[r0 + s + 8] = h; g_vtl[r0 + s + 8] = __float2bfloat16(v2 - __bfloat162float(h));
            h = __float2bfloat16(v3);
            g_vth[r1 + s + 8] = h; g_vtl[r1 + s + 8] = __float2bfloat16(v3 - __bfloat162float(h));
        }
    }
}

// ---------------------------------------------------------------------------
// Kernel 2: attn5 — 128-query CTAs, 8 warps, per-warp work identical to attn3.
// Grid (32 qtiles, 4 batches) x 256 threads. Dyn smem 96 KB:
//   stage0 @0, stage1 @32768 : [KH 8K | KL 8K | VH 8K | VL 8K]
//   QH @65536 (16K), QL @81920 (16K)
// ---------------------------------------------------------------------------
#define STAGE_BYTES 32768
#define QOFF 65536
#define ATTN_SMEM  98304

__device__ __forceinline__ void load_stage256(uint32_t sb, int b, int kt, int stage, int tid) {
    const int sel = tid >> 6;
    const int row = tid & 63;
    const bf16* src;
    if (sel == 0)      src = g_kh  + (size_t)(b * SS + kt * 64 + row) * 64;
    else if (sel == 1) src = g_kl  + (size_t)(b * SS + kt * 64 + row) * 64;
    else if (sel == 2) src = g_vth + (size_t)(b * HH + row) * SS + kt * 64;
    else               src = g_vtl + (size_t)(b * HH + row) * SS + kt * 64;
    const uint32_t dst = sb + stage * STAGE_BYTES + sel * 8192 + row * 128;
    const int sw = row & 7;
#pragma unroll
    for (int c = 0; c < 8; ++c) cp16(dst + ((c ^ sw) << 4), src + c * 8);
}

__global__ void __launch_bounds__(256, 1) attn5_kernel(float* __restrict__ out)
{
    extern __shared__ __align__(1024) unsigned char sm[];

    const int tid  = threadIdx.x;
    const int lane = tid & 31;
    const int wid  = tid >> 5;
    const int b    = blockIdx.y;
    const int tok0 = b * SS + blockIdx.x * 128;
    const uint32_t sb = smem_u32(sm);

    // Q prologue: 128 rows x {hi, lo}.
    {
        const int row = tid & 127;
        const int buf = tid >> 7;
        const bf16* src = (buf ? g_ql : g_qh) + (size_t)(tok0 + row) * 64;
        const int sw = row & 7;
        const uint32_t dst = sb + QOFF + buf * 16384 + row * 128;
#pragma unroll
        for (int c = 0; c < 8; ++c) cp16(dst + ((c ^ sw) << 4), src + c * 8);
    }
    CP_COMMIT();
    load_stage256(sb, b, 0, 0, tid);
    CP_COMMIT();
    load_stage256(sb, b, 1, 1, tid);
    CP_COMMIT();

    CP_WAIT(2);
    __syncthreads();
    uint32_t aQH[4][4], aQL[4][4];
    {
        const int g = lane >> 3, l = lane & 7;
        const int rowA = wid * 16 + l + ((g & 1) << 3);
        const int cA = g >> 1;
        const int swA = rowA & 7;
#pragma unroll
        for (int kc = 0; kc < 4; ++kc) {
            const uint32_t offA =
                (uint32_t)(rowA * 128 + ((((kc << 1) | cA) ^ swA) << 4));
            ldsm_x4(aQH[kc], sb + QOFF + offA);
            ldsm_x4(aQL[kc], sb + QOFF + 16384 + offA);
        }
    }

    float O[8][4] = {};
    float lsum0 = 0.f, lsum1 = 0.f;

    const int g = lane >> 3, l = lane & 7;
    const int rowB = l + ((g & 2) << 2);
    const int cB = g & 1;
    const int swB = rowB & 7;

    for (int kt = 0; kt < 64; ++kt) {
        CP_WAIT(1);
        __syncthreads();
        const uint32_t st = sb + (uint32_t)(kt & 1) * STAGE_BYTES;

        float S[8][4] = {};
#pragma unroll
        for (int kc = 0; kc < 4; ++kc) {
#pragma unroll
            for (int j2 = 0; j2 < 4; ++j2) {
                const uint32_t offB = (uint32_t)((j2 * 16 + rowB) * 128 +
                                     ((((kc << 1) | cB) ^ swB) << 4));
                uint32_t bh[4], bl[4];
                ldsm_x4(bh, st + offB);
                ldsm_x4(bl, st + 8192 + offB);
                mma_bf16(S[2*j2],   aQH[kc], bh[0], bh[1]);
                mma_bf16(S[2*j2+1], aQH[kc], bh[2], bh[3]);
                mma_bf16(S[2*j2],   aQH[kc], bl[0], bl[1]);
                mma_bf16(S[2*j2+1], aQH[kc], bl[2], bl[3]);
                mma_bf16(S[2*j2],   aQL[kc], bh[0], bh[1]);
                mma_bf16(S[2*j2+1], aQL[kc], bh[2], bh[3]);
            }
        }

        uint32_t aPH[4][4], aPL[4][4];
#pragma unroll
        for (int j = 0; j < 8; ++j) {
            u64 y01 = pack2(fmaxf(S[j][0], -100.f), fmaxf(S[j][1], -100.f));
            u64 y23 = pack2(fmaxf(S[j][2], -100.f), fmaxf(S[j][3], -100.f));
            float2 p01 = unpk2(exp2pair(y01));
            float2 p23 = unpk2(exp2pair(y23));
            lsum0 += p01.x + p01.y;
            lsum1 += p23.x + p23.y;
            uint32_t h01 = bfpack(p01.x, p01.y);
            uint32_t h23 = bfpack(p23.x, p23.y);
            uint32_t l01 = bfpack(p01.x - __uint_as_float(h01 << 16),
                                  p01.y - __uint_as_float(h01 & 0xFFFF0000u));
            uint32_t l23 = bfpack(p23.x - __uint_as_float(h23 << 16),
                                  p23.y - __uint_as_float(h23 & 0xFFFF0000u));
            aPH[j >> 1][(j & 1) * 2 + 0] = h01;
            aPH[j >> 1][(j & 1) * 2 + 1] = h23;
            aPL[j >> 1][(j & 1) * 2 + 0] = l01;
            aPL[j >> 1][(j & 1) * 2 + 1] = l23;
        }

#pragma unroll
        for (int kc = 0; kc < 4; ++kc) {
#pragma unroll
            for (int j2 = 0; j2 < 4; ++j2) {
                const uint32_t offB = (uint32_t)((j2 * 16 + rowB) * 128 +
                                     ((((kc << 1) | cB) ^ swB) << 4));
                uint32_t bh[4], bl[4];
                ldsm_x4(bh, st + 16384 + offB);
                ldsm_x4(bl, st + 24576 + offB);
                mma_bf16(O[2*j2],   aPH[kc], bh[0], bh[1]);
                mma_bf16(O[2*j2+1], aPH[kc], bh[2], bh[3]);
                mma_bf16(O[2*j2],   aPH[kc], bl[0], bl[1]);
                mma_bf16(O[2*j2+1], aPH[kc], bl[2], bl[3]);
                mma_bf16(O[2*j2],   aPL[kc], bh[0], bh[1]);
                mma_bf16(O[2*j2+1], aPL[kc], bh[2], bh[3]);
            }
        }

        __syncthreads();
        if (kt + 2 < 64) load_stage256(sb, b, kt + 2, kt & 1, tid);
        CP_COMMIT();
    }

    lsum0 += __shfl_xor_sync(0xffffffffu, lsum0, 1);
    lsum0 += __shfl_xor_sync(0xffffffffu, lsum0, 2);
    lsum1 += __shfl_xor_sync(0xffffffffu, lsum1, 1);
    lsum1 += __shfl_xor_sync(0xffffffffu, lsum1, 2);
    const float inv0 = 1.0f / lsum0;
    const float inv1 = 1.0f / lsum1;

    const int r  = lane >> 2;
    const int cc = (lane & 3) * 2;
    const size_t qrow = (size_t)tok0 + wid * 16 + r;
#pragma unroll
    for (int j = 0; j < 8; ++j) {
        float2* p0 = (float2*)(out + qrow * 64 + j * 8 + cc);
        *p0 = make_float2(O[j][0] * inv0, O[j][1] * inv0);
        float2* p1 = (float2*)(out + (qrow + 8) * 64 + j * 8 + cc);
        *p1 = make_float2(O[j][2] * inv1, O[j][3] * inv1);
    }
}

extern "C" void kernel_launch(void* const* d_in, const int* in_sizes, int n_in,
                              void* d_out, int out_size) {
    (void)in_sizes; (void)n_in; (void)out_size;
    const float* x  = (const float*)d_in[0];
    const float* Wq = (const float*)d_in[1];
    const float* bq = (const float*)d_in[2];
    const float* Wk = (const float*)d_in[3];
    const float* bk = (const float*)d_in[4];
    const float* Wv = (const float*)d_in[5];
    const float* bv = (const float*)d_in[6];

    cudaFuncSetAttribute(qkv_kernel,
                         cudaFuncAttributeMaxDynamicSharedMemorySize, QKV_SMEM);
    cudaFuncSetAttribute(attn5_kernel,
                         cudaFuncAttributeMaxDynamicSharedMemorySize, ATTN_SMEM);

    wsplit_kernel<<<96, 256>>>(Wq, Wk, Wv);
    qkv_kernel<<<128, 256, QKV_SMEM>>>(x, bq, bk, bv);
    attn5_kernel<<<dim3(32, 4), 256, ATTN_SMEM>>>((float*)d_out);
}

// round 9
// speedup vs baseline: 1.0755x; 1.0755x over previous
#include <cuda_runtime.h>
#include <cuda_bf16.h>
#include <cstdint>

#define BB 4
#define SS 4096
#define DD 512
#define HH 64

typedef unsigned long long u64;
typedef __nv_bfloat16 bf16;

// Split Q/K/V (Q pre-scaled by log2(e)/8), V transposed [b][h][s].
__device__ __align__(16) bf16 g_qh[BB*SS*HH];
__device__ __align__(16) bf16 g_ql[BB*SS*HH];
__device__ __align__(16) bf16 g_kh[BB*SS*HH];
__device__ __align__(16) bf16 g_kl[BB*SS*HH];
__device__ __align__(16) bf16 g_vth[BB*SS*HH];
__device__ __align__(16) bf16 g_vtl[BB*SS*HH];
// Pre-split transposed weights: [mat][h][d].
__device__ __align__(16) bf16 g_wth[3*HH*DD];
__device__ __align__(16) bf16 g_wtl[3*HH*DD];

// ======================= packed f32x2 / exp2 helpers ========================
__device__ __forceinline__ u64 dup2(float x) {
    u64 r; asm("mov.b64 %0, {%1, %1};" : "=l"(r) : "f"(x)); return r;
}
__device__ __forceinline__ u64 pack2(float x, float y) {
    u64 r; asm("mov.b64 %0, {%1, %2};" : "=l"(r) : "f"(x), "f"(y)); return r;
}
__device__ __forceinline__ float2 unpk2(u64 p) {
    float2 v; asm("mov.b64 {%0, %1}, %2;" : "=f"(v.x), "=f"(v.y) : "l"(p)); return v;
}
__device__ __forceinline__ u64 fma2o(u64 a, u64 b, u64 c) {
    u64 d; asm("fma.rn.f32x2 %0, %1, %2, %3;" : "=l"(d) : "l"(a), "l"(b), "l"(c));
    return d;
}
__device__ __forceinline__ u64 add2(u64 a, u64 b) {
    u64 d; asm("add.rn.f32x2 %0, %1, %2;" : "=l"(d) : "l"(a), "l"(b)); return d;
}
__device__ __forceinline__ u64 exp2pair(u64 y2) {
    const u64 MAGIC = dup2(12582912.0f);
    const u64 NEG1  = dup2(-1.0f);
    u64 t2 = add2(y2, MAGIC);
    u64 g2 = fma2o(MAGIC, NEG1, t2);
    u64 f2 = fma2o(g2, NEG1, y2);
    u64 p = dup2(1.3333558146428443e-3f);
    p = fma2o(p, f2, dup2(9.618129107628477e-3f));
    p = fma2o(p, f2, dup2(5.550410866482158e-2f));
    p = fma2o(p, f2, dup2(2.4022650695910072e-1f));
    p = fma2o(p, f2, dup2(6.931471805599453e-1f));
    p = fma2o(p, f2, dup2(1.0f));
    uint2 tb = *reinterpret_cast<uint2*>(&t2);
    uint2 pb = *reinterpret_cast<uint2*>(&p);
    pb.x += (tb.x << 23);
    pb.y += (tb.y << 23);
    return *reinterpret_cast<u64*>(&pb);
}
__device__ __forceinline__ uint32_t bfpack(float lo, float hi) {
    uint32_t r;
    asm("cvt.rn.bf16x2.f32 %0, %1, %2;" : "=r"(r) : "f"(hi), "f"(lo));
    return r;
}

// ======================= tensor-core primitives =============================
__device__ __forceinline__ uint32_t smem_u32(const void* p) {
    uint32_t a;
    asm("{ .reg .u64 t; cvta.to.shared.u64 t, %1; cvt.u32.u64 %0, t; }"
        : "=r"(a) : "l"(p));
    return a;
}
__device__ __forceinline__ void mma_bf16(float (&d)[4], const uint32_t (&a)[4],
                                         uint32_t b0, uint32_t b1) {
    asm volatile(
        "mma.sync.aligned.m16n8k16.row.col.f32.bf16.bf16.f32 "
        "{%0,%1,%2,%3}, {%4,%5,%6,%7}, {%8,%9}, {%0,%1,%2,%3};"
        : "+f"(d[0]), "+f"(d[1]), "+f"(d[2]), "+f"(d[3])
        : "r"(a[0]), "r"(a[1]), "r"(a[2]), "r"(a[3]), "r"(b0), "r"(b1));
}
__device__ __forceinline__ void ldsm_x4(uint32_t (&r)[4], uint32_t addr) {
    asm volatile("ldmatrix.sync.aligned.m8n8.x4.shared.b16 {%0,%1,%2,%3}, [%4];"
        : "=r"(r[0]), "=r"(r[1]), "=r"(r[2]), "=r"(r[3]) : "r"(addr));
}
__device__ __forceinline__ void cp16(uint32_t saddr, const void* gaddr) {
    asm volatile("cp.async.cg.shared.global [%0], [%1], 16;"
        :: "r"(saddr), "l"(gaddr));
}
#define CP_COMMIT() asm volatile("cp.async.commit_group;" ::: "memory")
#define CP_WAIT(n)  asm volatile("cp.async.wait_group %0;" :: "n"(n) : "memory")

// ---------------------------------------------------------------------------
// Kernel 0: pre-split W (transposed) into bf16 hi/lo. [mat][h][d]
// ---------------------------------------------------------------------------
__global__ void wsplit_kernel(const float* __restrict__ Wq,
                              const float* __restrict__ Wk,
                              const float* __restrict__ Wv) {
    int i = blockIdx.x * 256 + threadIdx.x;
#pragma unroll
    for (int e = 0; e < 4; ++e, i += 24576) {
        int mat = i >> 15;
        int rem = i & 32767;
        int h = rem >> 9;
        int d = rem & 511;
        const float* W = mat == 0 ? Wq : (mat == 1 ? Wk : Wv);
        float v = W[d * 64 + h];
        bf16 hi = __float2bfloat16(v);
        g_wth[i] = hi;
        g_wtl[i] = __float2bfloat16(v - __bfloat162float(hi));
    }
}

// ---------------------------------------------------------------------------
// Kernel 1: QKV projection via HMMA bf16x3 (round-7, verified ~54us).
// ---------------------------------------------------------------------------
#define QKV_XF(s) ((s) * 32768)
#define QKV_W(s)  (65536 + (s) * 49152)
#define QKV_XH    163840
#define QKV_XL    180224
#define QKV_SMEM  196608

__device__ __forceinline__ void qkv_load_x(uint32_t sb, const float* __restrict__ x,
                                           int row0, int kb, int slot, int tid) {
    const int row = tid >> 1;
    const int c0 = (tid & 1) * 8;
    const float* src = x + (size_t)(row0 + row) * 512 + kb * 64 + c0 * 4;
    const uint32_t dst = sb + QKV_XF(slot) + row * 256 + c0 * 16;
#pragma unroll
    for (int c = 0; c < 8; ++c) cp16(dst + c * 16, src + c * 4);
}

__device__ __forceinline__ void qkv_load_w(uint32_t sb, int kb, int slot, int tid) {
#pragma unroll
    for (int u = tid; u < 384; u += 256) {
        const int mat = u >> 7;
        const int half = (u >> 6) & 1;
        const int h = u & 63;
        const bf16* src = (half ? g_wtl : g_wth) + ((size_t)(mat * 64 + h)) * 512 + kb * 64;
        const uint32_t dst = sb + QKV_W(slot) + mat * 16384 + half * 8192 + h * 128;
        const int sw = h & 7;
#pragma unroll
        for (int c = 0; c < 8; ++c) cp16(dst + ((c ^ sw) << 4), src + c * 8);
    }
}

__global__ void __launch_bounds__(256, 1) qkv_kernel(
    const float* __restrict__ x,
    const float* __restrict__ bq, const float* __restrict__ bk,
    const float* __restrict__ bv)
{
    extern __shared__ __align__(1024) unsigned char sm[];
    const uint32_t sb = smem_u32(sm);

    const int tid  = threadIdx.x;
    const int lane = tid & 31;
    const int wid  = tid >> 5;
    const int row0 = blockIdx.x * 128;

    qkv_load_x(sb, x, row0, 0, 0, tid);
    qkv_load_w(sb, 0, 0, tid);
    CP_COMMIT();
    qkv_load_x(sb, x, row0, 1, 1, tid);
    qkv_load_w(sb, 1, 1, tid);
    CP_COMMIT();

    float acc[3][8][4] = {};

    const int g = lane >> 3, l = lane & 7;
    const int rowA = wid * 16 + l + ((g & 1) << 3);
    const int cA = g >> 1;
    const int swA = rowA & 7;
    const int rowB = l + ((g & 2) << 2);
    const int cB = g & 1;
    const int swB = rowB & 7;

    for (int kb = 0; kb < 8; ++kb) {
        CP_WAIT(1);
        __syncthreads();

        {
            const int row = tid >> 1;
            const int p0 = (tid & 1) * 16;
            const float* srow = (const float*)(sm + QKV_XF(kb & 1)) + row * 64;
#pragma unroll
            for (int pp = 0; pp < 16; ++pp) {
                const int cp = p0 + pp;
                float f0 = srow[cp * 2], f1 = srow[cp * 2 + 1];
                uint32_t h = bfpack(f0, f1);
                uint32_t lo = bfpack(f0 - __uint_as_float(h << 16),
                                     f1 - __uint_as_float(h & 0xFFFF0000u));
                const uint32_t a = (uint32_t)(row * 128 +
                                   (((cp >> 2) ^ (row & 7)) << 4) + (cp & 3) * 4);
                *(uint32_t*)(sm + QKV_XH + a) = h;
                *(uint32_t*)(sm + QKV_XL + a) = lo;
            }
        }
        __syncthreads();

        const uint32_t wbase = sb + QKV_W(kb & 1);
#pragma unroll
        for (int kc = 0; kc < 4; ++kc) {
            uint32_t aXH[4], aXL[4];
            const uint32_t offA = (uint32_t)(rowA * 128 +
                                 ((((kc << 1) | cA) ^ swA) << 4));
            ldsm_x4(aXH, sb + QKV_XH + offA);
            ldsm_x4(aXL, sb + QKV_XL + offA);
#pragma unroll
            for (int mat = 0; mat < 3; ++mat) {
#pragma unroll
                for (int jj = 0; jj < 4; ++jj) {
                    const uint32_t offB = (uint32_t)((jj * 16 + rowB) * 128 +
                                         ((((kc << 1) | cB) ^ swB) << 4));
                    uint32_t bh[4], bl[4];
                    ldsm_x4(bh, wbase + mat * 16384 + offB);
                    ldsm_x4(bl, wbase + mat * 16384 + 8192 + offB);
                    mma_bf16(acc[mat][2*jj],   aXH, bh[0], bh[1]);
                    mma_bf16(acc[mat][2*jj+1], aXH, bh[2], bh[3]);
                    mma_bf16(acc[mat][2*jj],   aXH, bl[0], bl[1]);
                    mma_bf16(acc[mat][2*jj+1], aXH, bl[2], bl[3]);
                    mma_bf16(acc[mat][2*jj],   aXL, bh[0], bh[1]);
                    mma_bf16(acc[mat][2*jj+1], aXL, bh[2], bh[3]);
                }
            }
        }
        __syncthreads();

        if (kb + 2 < 8) {
            qkv_load_x(sb, x, row0, kb + 2, kb & 1, tid);
            qkv_load_w(sb, kb + 2, kb & 1, tid);
        }
        CP_COMMIT();
    }

    const float QSC = 0.18033688011112042f;   // log2(e)/8
    const int r = lane >> 2;
    const int cq = (lane & 3);
    const int tok = row0 + wid * 16 + r;
    const int bb = blockIdx.x >> 5;
    const int s  = (row0 & (SS - 1)) + wid * 16 + r;

    uint32_t* qhA = (uint32_t*)(g_qh + (size_t)tok * 64);
    uint32_t* qlA = (uint32_t*)(g_ql + (size_t)tok * 64);
    uint32_t* qhB = (uint32_t*)(g_qh + (size_t)(tok + 8) * 64);
    uint32_t* qlB = (uint32_t*)(g_ql + (size_t)(tok + 8) * 64);
    uint32_t* khA = (uint32_t*)(g_kh + (size_t)tok * 64);
    uint32_t* klA = (uint32_t*)(g_kl + (size_t)tok * 64);
    uint32_t* khB = (uint32_t*)(g_kh + (size_t)(tok + 8) * 64);
    uint32_t* klB = (uint32_t*)(g_kl + (size_t)(tok + 8) * 64);

#pragma unroll
    for (int j = 0; j < 8; ++j) {
        const int u32idx = j * 4 + cq;
        const float2 b2q = ((const float2*)bq)[u32idx];
        const float2 b2k = ((const float2*)bk)[u32idx];
        const float2 b2v = ((const float2*)bv)[u32idx];

        {
            float v0 = (acc[0][j][0] + b2q.x) * QSC;
            float v1 = (acc[0][j][1] + b2q.y) * QSC;
            float v2 = (acc[0][j][2] + b2q.x) * QSC;
            float v3 = (acc[0][j][3] + b2q.y) * QSC;
            uint32_t h0 = bfpack(v0, v1), h1 = bfpack(v2, v3);
            qhA[u32idx] = h0;
            qhB[u32idx] = h1;
            qlA[u32idx] = bfpack(v0 - __uint_as_float(h0 << 16),
                                 v1 - __uint_as_float(h0 & 0xFFFF0000u));
            qlB[u32idx] = bfpack(v2 - __uint_as_float(h1 << 16),
                                 v3 - __uint_as_float(h1 & 0xFFFF0000u));
        }
        {
            float v0 = acc[1][j][0] + b2k.x;
            float v1 = acc[1][j][1] + b2k.y;
            float v2 = acc[1][j][2] + b2k.x;
            float v3 = acc[1][j][3] + b2k.y;
            uint32_t h0 = bfpack(v0, v1), h1 = bfpack(v2, v3);
            khA[u32idx] = h0;
            khB[u32idx] = h1;
            klA[u32idx] = bfpack(v0 - __uint_as_float(h0 << 16),
                                 v1 - __uint_as_float(h0 & 0xFFFF0000u));
            klB[u32idx] = bfpack(v2 - __uint_as_float(h1 << 16),
                                 v3 - __uint_as_float(h1 & 0xFFFF0000u));
        }
        {
            const int c0 = j * 8 + cq * 2;
            float v0 = acc[2][j][0] + b2v.x;
            float v1 = acc[2][j][1] + b2v.y;
            float v2 = acc[2][j][2] + b2v.x;
            float v3 = acc[2][j][3] + b2v.y;
            size_t r0 = ((size_t)(bb * 64 + c0)) * SS;
            size_t r1 = r0 + SS;
            bf16 h;
            h = __float2bfloat16(v0);
            g_vth[r0 + s] = h; g_vtl[r0 + s] = __float2bfloat16(v0 - __bfloat162float(h));
            h = __float2bfloat16(v1);
            g_vth[r1 + s] = h; g_vtl[r1 + s] = __float2bfloat16(v1 - __bfloat162float(h));
            h = __float2bfloat16(v2);
            g_vth[r0 + s + 8] = h; g_vtl[r0 + s + 8] = __float2bfloat16(v2 - __bfloat162float(h));
            h = __float2bfloat16(v3);
            g_vth[r1 + s + 8] = h; g_vtl[r1 + s + 8] = __float2bfloat16(v3 - __bfloat162float(h));
        }
    }
}

// ---------------------------------------------------------------------------
// Kernel 2: attn7 — attn3 body with a 3-stage ring and ONE barrier per tile.
// Grid (64 qtiles, 4 batches) x 128 threads. Dyn smem 112 KB:
//   stage s @ s*32768 (s=0,1,2): [KH 8K | KL 8K | VH 8K | VL 8K]
//   Q @98304: [QH 8K | QL 8K]
// ---------------------------------------------------------------------------
#define STAGE_BYTES 32768
#define QOFF 98304
#define ATTN_SMEM (QOFF + 16384)

__device__ __forceinline__ void load_stage128(uint32_t sb, int b, int kt, int stage, int tid) {
    const int row = tid >> 1;
    const int c0 = (tid & 1) * 4;
    const int sw = row & 7;
    const uint32_t sbase = sb + stage * STAGE_BYTES + row * 128;
    const bf16* kh = g_kh  + (size_t)(b * SS + kt * 64 + row) * 64;
    const bf16* kl = g_kl  + (size_t)(b * SS + kt * 64 + row) * 64;
    const bf16* vh = g_vth + (size_t)(b * HH + row) * SS + kt * 64;
    const bf16* vl = g_vtl + (size_t)(b * HH + row) * SS + kt * 64;
#pragma unroll
    for (int c = 0; c < 4; ++c) {
        const int ch = c0 + c;
        const uint32_t so = (uint32_t)((ch ^ sw) << 4);
        cp16(sbase + so,         kh + ch * 8);
        cp16(sbase + 8192 + so,  kl + ch * 8);
        cp16(sbase + 16384 + so, vh + ch * 8);
        cp16(sbase + 24576 + so, vl + ch * 8);
    }
}

__global__ void __launch_bounds__(128, 2) attn7_kernel(float* __restrict__ out)
{
    extern __shared__ __align__(1024) unsigned char sm[];

    const int tid  = threadIdx.x;
    const int lane = tid & 31;
    const int wid  = tid >> 5;
    const int qt = blockIdx.x;
    const int b  = blockIdx.y;
    const int tok0 = b * SS + qt * 64;
    const uint32_t sb = smem_u32(sm);

    // Prologue groups: Q, tile0, tile1.
    {
        const int row = tid >> 1;
        const int c0 = (tid & 1) * 4;
        const int sw = row & 7;
        const bf16* qh = g_qh + (size_t)(tok0 + row) * 64;
        const bf16* ql = g_ql + (size_t)(tok0 + row) * 64;
#pragma unroll
        for (int c = 0; c < 4; ++c) {
            const int ch = c0 + c;
            const uint32_t so = (uint32_t)(row * 128 + ((ch ^ sw) << 4));
            cp16(sb + QOFF + so,        qh + ch * 8);
            cp16(sb + QOFF + 8192 + so, ql + ch * 8);
        }
    }
    CP_COMMIT();
    load_stage128(sb, b, 0, 0, tid);
    CP_COMMIT();
    load_stage128(sb, b, 1, 1, tid);
    CP_COMMIT();

    // Q fragments (Q group done; tiles 0,1 still possibly in flight).
    CP_WAIT(2);
    __syncthreads();
    uint32_t aQH[4][4], aQL[4][4];
    {
        const int g = lane >> 3, l = lane & 7;
        const int rowA = wid * 16 + l + ((g & 1) << 3);
        const int cA = g >> 1;
        const int swA = rowA & 7;
#pragma unroll
        for (int kc = 0; kc < 4; ++kc) {
            const uint32_t offA =
                (uint32_t)(rowA * 128 + ((((kc << 1) | cA) ^ swA) << 4));
            ldsm_x4(aQH[kc], sb + QOFF + offA);
            ldsm_x4(aQL[kc], sb + QOFF + 8192 + offA);
        }
    }

    float O[8][4] = {};
    float lsum0 = 0.f, lsum1 = 0.f;

    const int g = lane >> 3, l = lane & 7;
    const int rowB = l + ((g & 2) << 2);
    const int cB = g & 1;
    const int swB = rowB & 7;

    int stage = 0;       // stage of tile kt
    int lstage = 2;      // ring slot for tile kt+2
    for (int kt = 0; kt < 64; ++kt) {
        CP_WAIT(1);          // tile kt's group complete
        __syncthreads();     // visibility + all warps past phase kt-1 reads

        // Issue loads for tile kt+2 into the slot read in phase kt-1.
        if (kt + 2 < 64) load_stage128(sb, b, kt + 2, lstage, tid);
        CP_COMMIT();
        if (++lstage == 3) lstage = 0;

        const uint32_t st = sb + (uint32_t)stage * STAGE_BYTES;
        if (++stage == 3) stage = 0;

        float S[8][4] = {};
#pragma unroll
        for (int kc = 0; kc < 4; ++kc) {
#pragma unroll
            for (int j2 = 0; j2 < 4; ++j2) {
                const uint32_t offB = (uint32_t)((j2 * 16 + rowB) * 128 +
                                     ((((kc << 1) | cB) ^ swB) << 4));
                uint32_t bh[4], bl[4];
                ldsm_x4(bh, st + offB);
                ldsm_x4(bl, st + 8192 + offB);
                mma_bf16(S[2*j2],   aQH[kc], bh[0], bh[1]);
                mma_bf16(S[2*j2+1], aQH[kc], bh[2], bh[3]);
                mma_bf16(S[2*j2],   aQH[kc], bl[0], bl[1]);
                mma_bf16(S[2*j2+1], aQH[kc], bl[2], bl[3]);
                mma_bf16(S[2*j2],   aQL[kc], bh[0], bh[1]);
                mma_bf16(S[2*j2+1], aQL[kc], bh[2], bh[3]);
            }
        }

        uint32_t aPH[4][4], aPL[4][4];
#pragma unroll
        for (int j = 0; j < 8; ++j) {
            u64 y01 = pack2(fmaxf(S[j][0], -100.f), fmaxf(S[j][1], -100.f));
            u64 y23 = pack2(fmaxf(S[j][2], -100.f), fmaxf(S[j][3], -100.f));
            float2 p01 = unpk2(exp2pair(y01));
            float2 p23 = unpk2(exp2pair(y23));
            lsum0 += p01.x + p01.y;
            lsum1 += p23.x + p23.y;
            uint32_t h01 = bfpack(p01.x, p01.y);
            uint32_t h23 = bfpack(p23.x, p23.y);
            uint32_t l01 = bfpack(p01.x - __uint_as_float(h01 << 16),
                                  p01.y - __uint_as_float(h01 & 0xFFFF0000u));
            uint32_t l23 = bfpack(p23.x - __uint_as_float(h23 << 16),
                                  p23.y - __uint_as_float(h23 & 0xFFFF0000u));
            aPH[j >> 1][(j & 1) * 2 + 0] = h01;
            aPH[j >> 1][(j & 1) * 2 + 1] = h23;
            aPL[j >> 1][(j & 1) * 2 + 0] = l01;
            aPL[j >> 1][(j & 1) * 2 + 1] = l23;
        }

#pragma unroll
        for (int kc = 0; kc < 4; ++kc) {
#pragma unroll
            for (int j2 = 0; j2 < 4; ++j2) {
                const uint32_t offB = (uint32_t)((j2 * 16 + rowB) * 128 +
                                     ((((kc << 1) | cB) ^ swB) << 4));
                uint32_t bh[4], bl[4];
                ldsm_x4(bh, st + 16384 + offB);
                ldsm_x4(bl, st + 24576 + offB);
                mma_bf16(O[2*j2],   aPH[kc], bh[0], bh[1]);
                mma_bf16(O[2*j2+1], aPH[kc], bh[2], bh[3]);
                mma_bf16(O[2*j2],   aPH[kc], bl[0], bl[1]);
                mma_bf16(O[2*j2+1], aPH[kc], bl[2], bl[3]);
                mma_bf16(O[2*j2],   aPL[kc], bh[0], bh[1]);
                mma_bf16(O[2*j2+1], aPL[kc], bh[2], bh[3]);
            }
        }
        // no trailing barrier — next phase's single sync covers the WAR hazard
    }

    lsum0 += __shfl_xor_sync(0xffffffffu, lsum0, 1);
    lsum0 += __shfl_xor_sync(0xffffffffu, lsum0, 2);
    lsum1 += __shfl_xor_sync(0xffffffffu, lsum1, 1);
    lsum1 += __shfl_xor_sync(0xffffffffu, lsum1, 2);
    const float inv0 = 1.0f / lsum0;
    const float inv1 = 1.0f / lsum1;

    const int r  = lane >> 2;
    const int cc = (lane & 3) * 2;
    const size_t qrow = (size_t)tok0 + wid * 16 + r;
#pragma unroll
    for (int j = 0; j < 8; ++j) {
        float2* p0 = (float2*)(out + qrow * 64 + j * 8 + cc);
        *p0 = make_float2(O[j][0] * inv0, O[j][1] * inv0);
        float2* p1 = (float2*)(out + (qrow + 8) * 64 + j * 8 + cc);
        *p1 = make_float2(O[j][2] * inv1, O[j][3] * inv1);
    }
}

extern "C" void kernel_launch(void* const* d_in, const int* in_sizes, int n_in,
                              void* d_out, int out_size) {
    (void)in_sizes; (void)n_in; (void)out_size;
    const float* x  = (const float*)d_in[0];
    const float* Wq = (const float*)d_in[1];
    const float* bq = (const float*)d_in[2];
    const float* Wk = (const float*)d_in[3];
    const float* bk = (const float*)d_in[4];
    const float* Wv = (const float*)d_in[5];
    const float* bv = (const float*)d_in[6];

    cudaFuncSetAttribute(qkv_kernel,
                         cudaFuncAttributeMaxDynamicSharedMemorySize, QKV_SMEM);
    cudaFuncSetAttribute(attn7_kernel,
                         cudaFuncAttributeMaxDynamicSharedMemorySize, ATTN_SMEM);

    wsplit_kernel<<<96, 256>>>(Wq, Wk, Wv);
    qkv_kernel<<<128, 256, QKV_SMEM>>>(x, bq, bk, bv);
    attn7_kernel<<<dim3(64, 4), 128, ATTN_SMEM>>>((float*)d_out);
}